// round 15
// baseline (speedup 1.0000x reference)
#include <cuda_runtime.h>
#include <cuda_fp16.h>
#include <cstdint>
#include <math.h>

#define S_LEN 4096
#define E_DIM 1024
#define D_DIM 1024

typedef __half h16;

// ---------------- scratch (device globals; no allocation allowed) ----------
__device__ h16   g_xh[(size_t)S_LEN * E_DIM];
__device__ h16   g_xl[(size_t)S_LEN * E_DIM];
__device__ h16   g_Wqh[(size_t)E_DIM * D_DIM];
__device__ h16   g_Wql[(size_t)E_DIM * D_DIM];
__device__ h16   g_Wkh[(size_t)E_DIM * D_DIM];
__device__ h16   g_Wkl[(size_t)E_DIM * D_DIM];
__device__ h16   g_Wvth[(size_t)D_DIM * E_DIM];     // Wv^T hi only
__device__ h16   g_Mth[(size_t)E_DIM * E_DIM];      // (Wq Wk^T)^T split
__device__ h16   g_Mtl[(size_t)E_DIM * E_DIM];
__device__ h16   g_Th[(size_t)S_LEN * E_DIM];       // T = x M, split
__device__ h16   g_Tl[(size_t)S_LEN * E_DIM];
__device__ h16   g_Vth[(size_t)D_DIM * S_LEN];      // V^T fp16
__device__ float g_Pf[(size_t)S_LEN * S_LEN];       // raw scores (lower tri)
__device__ int   g_rowmax[S_LEN];
// dependency flags
__device__ int   g_wqk, g_wvt, g_xs;
__device__ int   g_mdone;
__device__ int   g_vdone[8];
__device__ int   g_tdone[32];
__device__ int   g_sdone[32];

// ---------------- PTX helpers (sm_80-compatible only) -----------------------
__device__ __forceinline__ uint32_t smem_u32(const void* p) {
    uint32_t a;
    asm("{ .reg .u64 t; cvta.to.shared.u64 t, %1; cvt.u32.u64 %0, t; }" : "=r"(a) : "l"(p));
    return a;
}

#define CP_ASYNC16(saddr, gaddr) \
    asm volatile("cp.async.cg.shared.global [%0], [%1], 16;" \
                 :: "r"(saddr), "l"(gaddr) : "memory")
#define CP_COMMIT() asm volatile("cp.async.commit_group;" ::: "memory")
#define CP_WAIT(N)  asm volatile("cp.async.wait_group %0;" :: "n"(N) : "memory")

#define LDSM4(r0, r1, r2, r3, addr) \
    asm volatile("ldmatrix.sync.aligned.m8n8.x4.shared.b16 {%0,%1,%2,%3}, [%4];" \
                 : "=r"(r0), "=r"(r1), "=r"(r2), "=r"(r3) : "r"(addr))

#define MMA16816(c0, c1, c2, c3, a0, a1, a2, a3, b0, b1) \
    asm volatile("mma.sync.aligned.m16n8k16.row.col.f32.f16.f16.f32 " \
                 "{%0,%1,%2,%3}, {%4,%5,%6,%7}, {%8,%9}, {%0,%1,%2,%3};" \
                 : "+f"(c0), "+f"(c1), "+f"(c2), "+f"(c3) \
                 : "r"(a0), "r"(a1), "r"(a2), "r"(a3), "r"(b0), "r"(b1))

__device__ __forceinline__ int encf(float x) {
    int i = __float_as_int(x);
    return (i >= 0) ? i : (i ^ 0x7FFFFFFF);
}
__device__ __forceinline__ float decf(int i) {
    return __int_as_float((i >= 0) ? i : (i ^ 0x7FFFFFFF));
}

__device__ __forceinline__ void spin_ge(int* f, int tgt) {
    while (atomicAdd(f, 0) < tgt) __nanosleep(128);
}

// split a float4 into two half2 (hi) + two half2 (lo)
__device__ __forceinline__ void split4(float4 v, uint32_t& h01, uint32_t& h23,
                                       uint32_t& l01, uint32_t& l23)
{
    __half2 a = __floats2half2_rn(v.x, v.y);
    __half2 b = __floats2half2_rn(v.z, v.w);
    float2 fa = __half22float2(a), fb = __half22float2(b);
    __half2 la = __floats2half2_rn(v.x - fa.x, v.y - fa.y);
    __half2 lb = __floats2half2_rn(v.z - fb.x, v.w - fb.y);
    h01 = *(uint32_t*)&a; h23 = *(uint32_t*)&b;
    l01 = *(uint32_t*)&la; l23 = *(uint32_t*)&lb;
}

// ---------------- init: flag + rowmax resets (1 CTA) -------------------------
__global__ void init_flags()
{
    const int tid = threadIdx.x;
    if (tid == 0) { g_wqk = 0; g_wvt = 0; g_xs = 0; g_mdone = 0; }
    if (tid < 8)  g_vdone[tid] = 0;
    if (tid < 32) { g_tdone[tid] = 0; g_sdone[tid] = 0; }
    for (int i = tid; i < S_LEN; i += 256) g_rowmax[i] = 0x80000000;
}

// ---------------- GEMM core (round-12 exact) ----------------------------------
#define RSB     80
#define TILE_B  (128 * RSB)              // 10240
#define SMEM_MEGA (2 * 4 * TILE_B + 1024)   // 82944

template <int NPROD>
__device__ __forceinline__ void gemm_core(
    uint32_t tiles, const h16* __restrict__ A0, const h16* __restrict__ A1,
    const h16* __restrict__ B0, const h16* __restrict__ B1,
    int Ktot, int NC, float (&acc)[4][4][4])
{
    constexpr int NTILES = (NPROD == 3) ? 4 : 2;
    constexpr uint32_t STAGE_B = NTILES * TILE_B;

    const int tid = threadIdx.x;
    const int wid = tid >> 5;
    const int lane = tid & 31;
    const int wm = wid >> 2;
    const int wn = wid & 3;

#pragma unroll
    for (int i = 0; i < 4; i++)
#pragma unroll
        for (int j = 0; j < 4; j++)
#pragma unroll
            for (int k = 0; k < 4; k++) acc[i][j][k] = 0.0f;

    auto load_stage = [&](int c) {
        const uint32_t st = tiles + (uint32_t)(c & 1) * STAGE_B;
        const int k0 = c * 32;
        const h16* srcs[NTILES];
        if (NPROD == 3) {
            srcs[0] = A0 + k0; srcs[1] = A1 + k0;
            srcs[2] = B0 + k0; srcs[3] = B1 + k0;
        } else {
            srcs[0] = A0 + k0; srcs[1] = B0 + k0;
        }
#pragma unroll
        for (int t = 0; t < NTILES; t++) {
#pragma unroll
            for (int j2 = 0; j2 < 2; j2++) {
                int j = tid + j2 * 256;
                int row = j >> 2, ck = j & 3;
                const void* g = srcs[t] + (size_t)row * Ktot + ck * 8;
                uint32_t s = st + (uint32_t)t * TILE_B + row * RSB + ck * 16;
                CP_ASYNC16(s, g);
            }
        }
        CP_COMMIT();
    };

    load_stage(0);

    const int lr15 = lane & 15;
    const int lhi16 = (lane >> 4) * 16;
    const int l7 = lane & 7;
    const int bmat = lane >> 3;
    const int bnsub = (bmat >> 1) * 8;
    const int bkb = (bmat & 1) * 16;

    for (int c = 0; c < NC; c++) {
        CP_WAIT(0);
        __syncthreads();

        const uint32_t st = tiles + (uint32_t)(c & 1) * STAGE_B;
        const uint32_t aHb = st + (uint32_t)(wm * 64) * RSB;
        const uint32_t aLb = aHb + TILE_B;
        const uint32_t bHb = st + (uint32_t)(NTILES / 2) * TILE_B
                                + (uint32_t)(wn * 32) * RSB;
        const uint32_t bLb = bHb + TILE_B;

#pragma unroll
        for (int ks = 0; ks < 2; ks++) {
            const uint32_t akb  = (uint32_t)(ks * 32 + lhi16);
            const uint32_t bkb2 = (uint32_t)(ks * 32) + bkb;

            uint32_t ah[4][4], al[4][4], bh[2][4], bl[2][4];
#pragma unroll
            for (int mi = 0; mi < 4; mi++) {
                uint32_t ra = (uint32_t)(mi * 16 + lr15) * RSB + akb;
                LDSM4(ah[mi][0], ah[mi][1], ah[mi][2], ah[mi][3], aHb + ra);
                if (NPROD == 3)
                    LDSM4(al[mi][0], al[mi][1], al[mi][2], al[mi][3], aLb + ra);
            }
#pragma unroll
            for (int pi = 0; pi < 2; pi++) {
                uint32_t rb = (uint32_t)(pi * 16 + bnsub + l7) * RSB + bkb2;
                LDSM4(bh[pi][0], bh[pi][1], bh[pi][2], bh[pi][3], bHb + rb);
                if (NPROD == 3)
                    LDSM4(bl[pi][0], bl[pi][1], bl[pi][2], bl[pi][3], bLb + rb);
            }
            // hh group first: fill the tensor queue
#pragma unroll
            for (int mi = 0; mi < 4; mi++)
#pragma unroll
                for (int ni = 0; ni < 4; ni++) {
                    const int pi = ni >> 1, j = (ni & 1) * 2;
                    float* a4 = acc[mi][ni];
                    MMA16816(a4[0], a4[1], a4[2], a4[3],
                             ah[mi][0], ah[mi][1], ah[mi][2], ah[mi][3],
                             bh[pi][j], bh[pi][j + 1]);
                }
            // issue next-stage loads under the tensor shadow
            if (ks == 0 && c + 1 < NC) load_stage(c + 1);
            if (NPROD == 3) {
#pragma unroll
                for (int mi = 0; mi < 4; mi++)
#pragma unroll
                    for (int ni = 0; ni < 4; ni++) {
                        const int pi = ni >> 1, j = (ni & 1) * 2;
                        float* a4 = acc[mi][ni];
                        MMA16816(a4[0], a4[1], a4[2], a4[3],
                                 ah[mi][0], ah[mi][1], ah[mi][2], ah[mi][3],
                                 bl[pi][j], bl[pi][j + 1]);
                    }
#pragma unroll
                for (int mi = 0; mi < 4; mi++)
#pragma unroll
                    for (int ni = 0; ni < 4; ni++) {
                        const int pi = ni >> 1, j = (ni & 1) * 2;
                        float* a4 = acc[mi][ni];
                        MMA16816(a4[0], a4[1], a4[2], a4[3],
                                 al[mi][0], al[mi][1], al[mi][2], al[mi][3],
                                 bh[pi][j], bh[pi][j + 1]);
                    }
            }
        }
    }
}

__device__ __forceinline__ void store_split(
    float (&acc)[4][4][4], h16* __restrict__ oh, h16* __restrict__ ol,
    int m0, int n0, int ldc)
{
    const int lane = threadIdx.x & 31;
    const int wm = (threadIdx.x >> 5) >> 2, wn = (threadIdx.x >> 5) & 3;
    const int gr = lane >> 2, gc = (lane & 3) << 1;
#pragma unroll
    for (int mi = 0; mi < 4; mi++) {
#pragma unroll
        for (int ni = 0; ni < 4; ni++) {
            const int rr = m0 + wm * 64 + mi * 16 + gr;
            const int cc = n0 + wn * 32 + ni * 8 + gc;
            float v0 = acc[mi][ni][0], v1 = acc[mi][ni][1];
            float v2 = acc[mi][ni][2], v3 = acc[mi][ni][3];
            h16 h0 = __float2half_rn(v0), h1 = __float2half_rn(v1);
            h16 h2 = __float2half_rn(v2), h3 = __float2half_rn(v3);
            __half2 hi01 = __halves2half2(h0, h1);
            __half2 hi23 = __halves2half2(h2, h3);
            __half2 lo01 = __halves2half2(__float2half_rn(v0 - __half2float(h0)),
                                          __float2half_rn(v1 - __half2float(h1)));
            __half2 lo23 = __halves2half2(__float2half_rn(v2 - __half2float(h2)),
                                          __float2half_rn(v3 - __half2float(h3)));
            *(__half2*)&oh[(size_t)rr * ldc + cc]       = hi01;
            *(__half2*)&ol[(size_t)rr * ldc + cc]       = lo01;
            *(__half2*)&oh[(size_t)(rr + 8) * ldc + cc] = hi23;
            *(__half2*)&ol[(size_t)(rr + 8) * ldc + cc] = lo23;
        }
    }
}

// ---------------- mega kernel ------------------------------------------------
// bid: [0,32) Wq/Wk split | [32,64) Wv^T | [64,192) x split | [192,256) M |
//      [256,512) V | [512,768) T desc | [768,1296) scores desc | [1296,1552) PV
__global__ __launch_bounds__(256, 2)
void mm_mega(float* __restrict__ out,
             const float* __restrict__ x,  const float* __restrict__ Wq,
             const float* __restrict__ Wk, const float* __restrict__ Wv)
{
    extern __shared__ char smem[];
    const uint32_t sbase = smem_u32(smem);
    const uint32_t tiles = (sbase + 127u) & ~127u;
    const uint32_t rel = tiles - sbase;
    const int tid = threadIdx.x;
    const int bid = blockIdx.x;
    const int lane = tid & 31;
    const int wid = tid >> 5;
    const int wm = wid >> 2, wn = wid & 3;
    const int gr = lane >> 2, gc = (lane & 3) << 1;

    if (bid < 32) {                       // ---- split Wq, Wk (vectorized) ----
        const int NW4 = (E_DIM * D_DIM) / 4;   // 262144 float4
        const float4* q4 = (const float4*)Wq;
        const float4* k4 = (const float4*)Wk;
        for (int i = bid * 256 + tid; i < NW4; i += 32 * 256) {
            uint32_t h01, h23, l01, l23;
            split4(q4[i], h01, h23, l01, l23);
            ((uint2*)g_Wqh)[i] = make_uint2(h01, h23);
            ((uint2*)g_Wql)[i] = make_uint2(l01, l23);
            split4(k4[i], h01, h23, l01, l23);
            ((uint2*)g_Wkh)[i] = make_uint2(h01, h23);
            ((uint2*)g_Wkl)[i] = make_uint2(l01, l23);
        }
        __threadfence(); __syncthreads();
        if (tid == 0) atomicAdd(&g_wqk, 1);
        return;
    }
    if (bid < 64) {                       // ---- Wv^T (hi only) ----
        float (*t)[33] = (float(*)[33])(smem + rel);
        const int u = bid - 32;
        const int tx = tid & 31, ty = tid >> 5;
        for (int k = u; k < 1024; k += 32) {
            const int bx = (k & 31) * 32;   // d
            const int by = (k >> 5) * 32;   // e
#pragma unroll
            for (int j = ty; j < 32; j += 8)
                t[j][tx] = Wv[(size_t)(by + j) * D_DIM + bx + tx];
            __syncthreads();
#pragma unroll
            for (int j = ty; j < 32; j += 8)
                g_Wvth[(size_t)(bx + j) * E_DIM + by + tx] = __float2half_rn(t[tx][j]);
            __syncthreads();
        }
        __threadfence();
        if (tid == 0) atomicAdd(&g_wvt, 1);
        return;
    }
    if (bid < 192) {                      // ---- split x (vectorized) ----
        const int NX4 = (S_LEN * E_DIM) / 4;   // 1048576 float4
        const float4* x4 = (const float4*)x;
        for (int i = (bid - 64) * 256 + tid; i < NX4; i += 128 * 256) {
            uint32_t h01, h23, l01, l23;
            split4(x4[i], h01, h23, l01, l23);
            ((uint2*)g_xh)[i] = make_uint2(h01, h23);
            ((uint2*)g_xl)[i] = make_uint2(l01, l23);
        }
        __threadfence(); __syncthreads();
        if (tid == 0) atomicAdd(&g_xs, 1);
        return;
    }
    if (bid < 256) {                      // ---- M = Wk · Wq^T ----
        const int u = bid - 192;
        const int m0 = (u >> 3) * 128, n0 = (u & 7) * 128;
        if (tid == 0) spin_ge(&g_wqk, 32);
        __syncthreads();
        float acc[4][4][4];
        gemm_core<3>(tiles,
                     g_Wkh + (size_t)m0 * D_DIM, g_Wkl + (size_t)m0 * D_DIM,
                     g_Wqh + (size_t)n0 * D_DIM, g_Wql + (size_t)n0 * D_DIM,
                     D_DIM, D_DIM / 32, acc);
        store_split(acc, g_Mth, g_Mtl, m0, n0, E_DIM);
        __threadfence(); __syncthreads();
        if (tid == 0) atomicAdd(&g_mdone, 1);
        return;
    }
    if (bid < 512) {                      // ---- V^T projection ----
        const int u = bid - 256;
        const int m0 = (u >> 5) * 128;    // d
        const int n0 = (u & 31) * 128;    // s
        if (tid == 0) { spin_ge(&g_wvt, 32); spin_ge(&g_xs, 128); }
        __syncthreads();
        float acc[4][4][4];
        gemm_core<1>(tiles,
                     g_Wvth + (size_t)m0 * E_DIM, nullptr,
                     g_xh + (size_t)n0 * E_DIM, nullptr,
                     E_DIM, E_DIM / 32, acc);
#pragma unroll
        for (int mi = 0; mi < 4; mi++)
#pragma unroll
            for (int ni = 0; ni < 4; ni++) {
                const int rr = m0 + wm * 64 + mi * 16 + gr;
                const int cc = n0 + wn * 32 + ni * 8 + gc;
                __half2 a = __halves2half2(__float2half_rn(acc[mi][ni][0]),
                                           __float2half_rn(acc[mi][ni][1]));
                __half2 b = __halves2half2(__float2half_rn(acc[mi][ni][2]),
                                           __float2half_rn(acc[mi][ni][3]));
                *(__half2*)&g_Vth[(size_t)rr * S_LEN + cc]       = a;
                *(__half2*)&g_Vth[(size_t)(rr + 8) * S_LEN + cc] = b;
            }
        __threadfence(); __syncthreads();
        if (tid == 0) atomicAdd(&g_vdone[u >> 5], 1);
        return;
    }
    if (bid < 768) {                      // ---- T = x · M (desc s) ----
        const int u = bid - 512;
        const int s = 31 - (u >> 3), b = u & 7;
        const int m0 = s * 128, n0 = b * 128;
        if (tid == 0) { spin_ge(&g_mdone, 64); spin_ge(&g_xs, 128); }
        __syncthreads();
        float acc[4][4][4];
        gemm_core<3>(tiles,
                     g_xh + (size_t)m0 * E_DIM, g_xl + (size_t)m0 * E_DIM,
                     g_Mth + (size_t)n0 * E_DIM, g_Mtl + (size_t)n0 * E_DIM,
                     E_DIM, E_DIM / 32, acc);
        store_split(acc, g_Th, g_Tl, m0, n0, E_DIM);
        __threadfence(); __syncthreads();
        if (tid == 0) atomicAdd(&g_tdone[s], 1);
        return;
    }
    if (bid < 1296) {                     // ---- scores (desc br) ----
        const int u = bid - 768;
        int t = 527 - u;
        int br = (int)((sqrtf(8.0f * (float)t + 1.0f) - 1.0f) * 0.5f);
        while ((br + 1) * (br + 2) / 2 <= t) br++;
        while (br * (br + 1) / 2 > t) br--;
        const int bc = t - br * (br + 1) / 2;
        const int m0 = br * 128, n0 = bc * 128;

        if (tid == 0) spin_ge(&g_tdone[br], 8);
        __syncthreads();

        float acc[4][4][4];
        gemm_core<3>(tiles,
                     g_Th + (size_t)m0 * E_DIM, g_Tl + (size_t)m0 * E_DIM,
                     g_xh + (size_t)n0 * E_DIM, g_xl + (size_t)n0 * E_DIM,
                     E_DIM, E_DIM / 32, acc);

        const bool diag = (bc == br);
        const float scale = 1.0f / 32.0f;
#pragma unroll
        for (int mi = 0; mi < 4; mi++) {
            const int r0 = m0 + wm * 64 + mi * 16 + gr;
            const int r1 = r0 + 8;
            float mx0 = -3.4e38f, mx1 = -3.4e38f;
#pragma unroll
            for (int ni = 0; ni < 4; ni++) {
                const int cc = n0 + wn * 32 + ni * 8 + gc;
                float v0 = acc[mi][ni][0] * scale;
                float v1 = acc[mi][ni][1] * scale;
                float v2 = acc[mi][ni][2] * scale;
                float v3 = acc[mi][ni][3] * scale;
                *(float2*)&g_Pf[(size_t)r0 * S_LEN + cc] = make_float2(v0, v1);
                *(float2*)&g_Pf[(size_t)r1 * S_LEN + cc] = make_float2(v2, v3);
                if (!diag || cc     <= r0) mx0 = fmaxf(mx0, v0);
                if (!diag || cc + 1 <= r0) mx0 = fmaxf(mx0, v1);
                if (!diag || cc     <= r1) mx1 = fmaxf(mx1, v2);
                if (!diag || cc + 1 <= r1) mx1 = fmaxf(mx1, v3);
            }
            mx0 = fmaxf(mx0, __shfl_xor_sync(0xffffffffu, mx0, 1));
            mx0 = fmaxf(mx0, __shfl_xor_sync(0xffffffffu, mx0, 2));
            mx1 = fmaxf(mx1, __shfl_xor_sync(0xffffffffu, mx1, 1));
            mx1 = fmaxf(mx1, __shfl_xor_sync(0xffffffffu, mx1, 2));
            if ((lane & 3) == 0) {
                atomicMax(&g_rowmax[r0], encf(mx0));
                atomicMax(&g_rowmax[r1], encf(mx1));
            }
        }
        __threadfence(); __syncthreads();
        if (tid == 0) atomicAdd(&g_sdone[br], 1);
        return;
    }

    // ---- PV with fused softmax (desc br) ----
    {
        const int u = bid - 1296;
        const int br = 31 - (u >> 3), bc = u & 7;
        const int m0 = br * 128, n0 = bc * 128;
        const int NC = (br + 1) * 4;

        if (tid == 0) { spin_ge(&g_sdone[br], br + 1); spin_ge(&g_vdone[bc], 32); }
        __syncthreads();

        const int prow = tid >> 1, ph = tid & 1;
        const int grow = m0 + prow;
        const float mrow = decf(g_rowmax[grow]);
        float rs = 0.0f;

        float acc[4][4][4];
#pragma unroll
        for (int i = 0; i < 4; i++)
#pragma unroll
            for (int j = 0; j < 4; j++)
#pragma unroll
                for (int k = 0; k < 4; k++) acc[i][j][k] = 0.0f;

        // stage: A(fp16 P) 10240 | B(Vt) 10240 | STG(fp32 Pf) 18432 = 38912
        auto load_pv = [&](int c) {
            const uint32_t st = tiles + (uint32_t)(c & 1) * 38912u;
            const int k0 = c * 32;
#pragma unroll
            for (int j4 = 0; j4 < 4; j4++) {
                int j = tid + j4 * 256;
                int r = j >> 3, ck = j & 7;
                const void* g = g_Pf + (size_t)(m0 + r) * S_LEN + k0 + ck * 4;
                CP_ASYNC16(st + 20480u + (uint32_t)(r * 144 + ck * 16), g);
            }
#pragma unroll
            for (int j2 = 0; j2 < 2; j2++) {
                int j = tid + j2 * 256;
                int r = j >> 2, ck = j & 3;
                const void* g = g_Vth + (size_t)(n0 + r) * S_LEN + k0 + ck * 8;
                CP_ASYNC16(st + 10240u + (uint32_t)(r * RSB + ck * 16), g);
            }
            CP_COMMIT();
        };

        load_pv(0);

        const int lr15 = lane & 15;
        const int lhi16 = (lane >> 4) * 16;
        const int l7 = lane & 7;
        const int bmat = lane >> 3;
        const int bnsub = (bmat >> 1) * 8;
        const int bkb = (bmat & 1) * 16;

        for (int c = 0; c < NC; c++) {
            CP_WAIT(0);
            __syncthreads();
            // convert Pf chunk -> exp fp16 into A tile; accumulate rowsum
            {
                const uint32_t srel = rel + (uint32_t)(c & 1) * 38912u;
                const float* sp = (const float*)(smem + srel + 20480u
                                                 + prow * 144 + ph * 64);
                float4 f0 = ((const float4*)sp)[0];
                float4 f1 = ((const float4*)sp)[1];
                float4 f2 = ((const float4*)sp)[2];
                float4 f3 = ((const float4*)sp)[3];
                float v[16] = {f0.x, f0.y, f0.z, f0.w, f1.x, f1.y, f1.z, f1.w,
                               f2.x, f2.y, f2.z, f2.w, f3.x, f3.y, f3.z, f3.w};
                const int kg = c * 32 + ph * 16;
                uint32_t w[8];
#pragma unroll
                for (int e = 0; e < 8; e++) {
                    float a = (kg + 2 * e     <= grow) ? __expf(v[2 * e]     - mrow) : 0.0f;
                    float b = (kg + 2 * e + 1 <= grow) ? __expf(v[2 * e + 1] - mrow) : 0.0f;
                    __half2 hh = __floats2half2_rn(a, b);
                    float2 fb = __half22float2(hh);
                    rs += fb.x + fb.y;
                    w[e] = *(uint32_t*)&hh;
                }
                uint4 q0 = make_uint4(w[0], w[1], w[2], w[3]);
                uint4 q1 = make_uint4(w[4], w[5], w[6], w[7]);
                *(uint4*)(smem + srel + prow * RSB + ph * 32)      = q0;
                *(uint4*)(smem + srel + prow * RSB + ph * 32 + 16) = q1;
            }
            __syncthreads();

            const uint32_t st = tiles + (uint32_t)(c & 1) * 38912u;
            const uint32_t aB = st + (uint32_t)(wm * 64) * RSB;
            const uint32_t bB = st + 10240u + (uint32_t)(wn * 32) * RSB;
#pragma unroll
            for (int ks = 0; ks < 2; ks++) {
                const uint32_t akb  = (uint32_t)(ks * 32 + lhi16);
                const uint32_t bkb2 = (uint32_t)(ks * 32) + bkb;
                uint32_t ah[4][4], bh[2][4];
#pragma unroll
                for (int mi = 0; mi < 4; mi++) {
                    uint32_t ra = aB + (uint32_t)(mi * 16 + lr15) * RSB + akb;
                    LDSM4(ah[mi][0], ah[mi][1], ah[mi][2], ah[mi][3], ra);
                }
#pragma unroll
                for (int pi = 0; pi < 2; pi++) {
                    uint32_t rb = bB + (uint32_t)(pi * 16 + bnsub + l7) * RSB + bkb2;
                    LDSM4(bh[pi][0], bh[pi][1], bh[pi][2], bh[pi][3], rb);
                }
#pragma unroll
                for (int mi = 0; mi < 4; mi++)
#pragma unroll
                    for (int ni = 0; ni < 4; ni++) {
                        const int pi = ni >> 1, j = (ni & 1) * 2;
                        float* a4 = acc[mi][ni];
                        MMA16816(a4[0], a4[1], a4[2], a4[3],
                                 ah[mi][0], ah[mi][1], ah[mi][2], ah[mi][3],
                                 bh[pi][j], bh[pi][j + 1]);
                    }
                if (ks == 0 && c + 1 < NC) load_pv(c + 1);
            }
        }

        float rtot = rs + __shfl_xor_sync(0xffffffffu, rs, 1);
        if ((tid & 1) == 0)
            *(float*)(smem + rel + 77824u + prow * 4) = rtot;
        __syncthreads();
        const float* rsum = (const float*)(smem + rel + 77824u);
#pragma unroll
        for (int mi = 0; mi < 4; mi++) {
            const int r0 = m0 + wm * 64 + mi * 16 + gr;
            const float inv0 = 1.0f / rsum[r0 - m0];
            const float inv1 = 1.0f / rsum[r0 - m0 + 8];
#pragma unroll
            for (int ni = 0; ni < 4; ni++) {
                const int cc = n0 + wn * 32 + ni * 8 + gc;
                *(float2*)&out[(size_t)r0 * D_DIM + cc] =
                    make_float2(acc[mi][ni][0] * inv0, acc[mi][ni][1] * inv0);
                *(float2*)&out[(size_t)(r0 + 8) * D_DIM + cc] =
                    make_float2(acc[mi][ni][2] * inv1, acc[mi][ni][3] * inv1);
            }
        }
    }
}

// ---------------- host launcher ---------------------------------------------
extern "C" void kernel_launch(void* const* d_in, const int* in_sizes, int n_in,
                              void* d_out, int out_size)
{
    const float* x  = (const float*)d_in[0];
    const float* Wq = (const float*)d_in[1];
    const float* Wk = (const float*)d_in[2];
    const float* Wv = (const float*)d_in[3];
    float* out = (float*)d_out;

    cudaFuncSetAttribute(mm_mega, cudaFuncAttributeMaxDynamicSharedMemorySize,
                         SMEM_MEGA);

    // 1) tiny init: flags + rowmax
    init_flags<<<1, 256>>>();
    // 2) everything: prep + all GEMMs in one dataflow launch
    mm_mega<<<1552, 256, SMEM_MEGA>>>(out, x, Wq, Wk, Wv);
}

// round 16
// speedup vs baseline: 1.5494x; 1.5494x over previous
#include <cuda_runtime.h>
#include <cuda_fp16.h>
#include <cstdint>
#include <math.h>

#define S_LEN 4096
#define E_DIM 1024
#define D_DIM 1024

typedef __half h16;

// ---------------- scratch (device globals; no allocation allowed) ----------
__device__ h16   g_xh[(size_t)S_LEN * E_DIM];
__device__ h16   g_xl[(size_t)S_LEN * E_DIM];
__device__ h16   g_Wqh[(size_t)E_DIM * D_DIM];
__device__ h16   g_Wql[(size_t)E_DIM * D_DIM];
__device__ h16   g_Wkh[(size_t)E_DIM * D_DIM];
__device__ h16   g_Wkl[(size_t)E_DIM * D_DIM];
__device__ h16   g_Wvth[(size_t)D_DIM * E_DIM];     // Wv^T hi only
__device__ h16   g_Mth[(size_t)E_DIM * E_DIM];      // (Wq Wk^T)^T split
__device__ h16   g_Mtl[(size_t)E_DIM * E_DIM];
__device__ h16   g_Th[(size_t)S_LEN * E_DIM];       // T = x M, split
__device__ h16   g_Tl[(size_t)S_LEN * E_DIM];
__device__ h16   g_Vth[(size_t)D_DIM * S_LEN];      // V^T fp16
__device__ float g_Pf[(size_t)S_LEN * S_LEN];       // raw scores (lower tri)
__device__ int   g_rowmax[S_LEN];
// dependency flags
__device__ int   g_mdone;
__device__ int   g_vdone[8];
__device__ int   g_tdone[32];
__device__ int   g_sdone[32];

// ---------------- PTX helpers (sm_80-compatible only) -----------------------
__device__ __forceinline__ uint32_t smem_u32(const void* p) {
    uint32_t a;
    asm("{ .reg .u64 t; cvta.to.shared.u64 t, %1; cvt.u32.u64 %0, t; }" : "=r"(a) : "l"(p));
    return a;
}

#define CP_ASYNC16(saddr, gaddr) \
    asm volatile("cp.async.cg.shared.global [%0], [%1], 16;" \
                 :: "r"(saddr), "l"(gaddr) : "memory")
#define CP_COMMIT() asm volatile("cp.async.commit_group;" ::: "memory")
#define CP_WAIT(N)  asm volatile("cp.async.wait_group %0;" :: "n"(N) : "memory")

#define LDSM4(r0, r1, r2, r3, addr) \
    asm volatile("ldmatrix.sync.aligned.m8n8.x4.shared.b16 {%0,%1,%2,%3}, [%4];" \
                 : "=r"(r0), "=r"(r1), "=r"(r2), "=r"(r3) : "r"(addr))

#define MMA16816(c0, c1, c2, c3, a0, a1, a2, a3, b0, b1) \
    asm volatile("mma.sync.aligned.m16n8k16.row.col.f32.f16.f16.f32 " \
                 "{%0,%1,%2,%3}, {%4,%5,%6,%7}, {%8,%9}, {%0,%1,%2,%3};" \
                 : "+f"(c0), "+f"(c1), "+f"(c2), "+f"(c3) \
                 : "r"(a0), "r"(a1), "r"(a2), "r"(a3), "r"(b0), "r"(b1))

__device__ __forceinline__ int encf(float x) {
    int i = __float_as_int(x);
    return (i >= 0) ? i : (i ^ 0x7FFFFFFF);
}
__device__ __forceinline__ float decf(int i) {
    return __int_as_float((i >= 0) ? i : (i ^ 0x7FFFFFFF));
}

__device__ __forceinline__ void spin_ge(int* f, int tgt) {
    while (atomicAdd(f, 0) < tgt) __nanosleep(128);
}

// split a float4 into two half2 (hi) + two half2 (lo)
__device__ __forceinline__ void split4(float4 v, uint32_t& h01, uint32_t& h23,
                                       uint32_t& l01, uint32_t& l23)
{
    __half2 a = __floats2half2_rn(v.x, v.y);
    __half2 b = __floats2half2_rn(v.z, v.w);
    float2 fa = __half22float2(a), fb = __half22float2(b);
    __half2 la = __floats2half2_rn(v.x - fa.x, v.y - fa.y);
    __half2 lb = __floats2half2_rn(v.z - fb.x, v.w - fb.y);
    h01 = *(uint32_t*)&a; h23 = *(uint32_t*)&b;
    l01 = *(uint32_t*)&la; l23 = *(uint32_t*)&lb;
}

// ---------------- prep: Wv^T tiles + vectorized splits + flag resets ---------
__global__ __launch_bounds__(256)
void prep(const float* __restrict__ x, const float* __restrict__ Wq,
          const float* __restrict__ Wk, const float* __restrict__ Wv)
{
    __shared__ float t[32][33];
    if (blockIdx.x < 1024) {
        const int u = blockIdx.x;
        const int bx = (u & 31) * 32;   // d
        const int by = (u >> 5) * 32;   // e
        const int tx = threadIdx.x & 31, ty = threadIdx.x >> 5;
#pragma unroll
        for (int j = ty; j < 32; j += 8)
            t[j][tx] = Wv[(size_t)(by + j) * D_DIM + bx + tx];
        __syncthreads();
#pragma unroll
        for (int j = ty; j < 32; j += 8)
            g_Wvth[(size_t)(bx + j) * E_DIM + by + tx] = __float2half_rn(t[tx][j]);
        return;
    }
    if (blockIdx.x == 1024) {
        if (threadIdx.x < 32) { g_tdone[threadIdx.x] = 0; g_sdone[threadIdx.x] = 0; }
        if (threadIdx.x < 8)  g_vdone[threadIdx.x] = 0;
        if (threadIdx.x == 0) g_mdone = 0;
    }
    const int g = (blockIdx.x - 1024) * 256 + threadIdx.x;
    const int stride = 2048 * 256;
    if (g < S_LEN) g_rowmax[g] = 0x80000000;

    const int NX4 = (S_LEN * E_DIM) / 4;
    const int NW4 = (E_DIM * D_DIM) / 4;
    const float4* x4 = (const float4*)x;
    const float4* q4 = (const float4*)Wq;
    const float4* k4 = (const float4*)Wk;
    uint32_t h01, h23, l01, l23;
    for (int i = g; i < NX4; i += stride) {
        split4(x4[i], h01, h23, l01, l23);
        ((uint2*)g_xh)[i] = make_uint2(h01, h23);
        ((uint2*)g_xl)[i] = make_uint2(l01, l23);
    }
    for (int i = g; i < NW4; i += stride) {
        split4(q4[i], h01, h23, l01, l23);
        ((uint2*)g_Wqh)[i] = make_uint2(h01, h23);
        ((uint2*)g_Wql)[i] = make_uint2(l01, l23);
    }
    for (int i = g; i < NW4; i += stride) {
        split4(k4[i], h01, h23, l01, l23);
        ((uint2*)g_Wkh)[i] = make_uint2(h01, h23);
        ((uint2*)g_Wkl)[i] = make_uint2(l01, l23);
    }
}

// ---------------- GEMM core (round-12 exact) ----------------------------------
#define RSB     80
#define TILE_B  (128 * RSB)              // 10240
#define SMEM_MEGA (2 * 4 * TILE_B + 1024)   // 82944

template <int NPROD>
__device__ __forceinline__ void gemm_core(
    uint32_t tiles, const h16* __restrict__ A0, const h16* __restrict__ A1,
    const h16* __restrict__ B0, const h16* __restrict__ B1,
    int Ktot, int NC, float (&acc)[4][4][4])
{
    constexpr int NTILES = (NPROD == 3) ? 4 : 2;
    constexpr uint32_t STAGE_B = NTILES * TILE_B;

    const int tid = threadIdx.x;
    const int wid = tid >> 5;
    const int lane = tid & 31;
    const int wm = wid >> 2;
    const int wn = wid & 3;

#pragma unroll
    for (int i = 0; i < 4; i++)
#pragma unroll
        for (int j = 0; j < 4; j++)
#pragma unroll
            for (int k = 0; k < 4; k++) acc[i][j][k] = 0.0f;

    auto load_stage = [&](int c) {
        const uint32_t st = tiles + (uint32_t)(c & 1) * STAGE_B;
        const int k0 = c * 32;
        const h16* srcs[NTILES];
        if (NPROD == 3) {
            srcs[0] = A0 + k0; srcs[1] = A1 + k0;
            srcs[2] = B0 + k0; srcs[3] = B1 + k0;
        } else {
            srcs[0] = A0 + k0; srcs[1] = B0 + k0;
        }
#pragma unroll
        for (int t = 0; t < NTILES; t++) {
#pragma unroll
            for (int j2 = 0; j2 < 2; j2++) {
                int j = tid + j2 * 256;
                int row = j >> 2, ck = j & 3;
                const void* g = srcs[t] + (size_t)row * Ktot + ck * 8;
                uint32_t s = st + (uint32_t)t * TILE_B + row * RSB + ck * 16;
                CP_ASYNC16(s, g);
            }
        }
        CP_COMMIT();
    };

    load_stage(0);

    const int lr15 = lane & 15;
    const int lhi16 = (lane >> 4) * 16;
    const int l7 = lane & 7;
    const int bmat = lane >> 3;
    const int bnsub = (bmat >> 1) * 8;
    const int bkb = (bmat & 1) * 16;

    for (int c = 0; c < NC; c++) {
        CP_WAIT(0);
        __syncthreads();

        const uint32_t st = tiles + (uint32_t)(c & 1) * STAGE_B;
        const uint32_t aHb = st + (uint32_t)(wm * 64) * RSB;
        const uint32_t aLb = aHb + TILE_B;
        const uint32_t bHb = st + (uint32_t)(NTILES / 2) * TILE_B
                                + (uint32_t)(wn * 32) * RSB;
        const uint32_t bLb = bHb + TILE_B;

#pragma unroll
        for (int ks = 0; ks < 2; ks++) {
            const uint32_t akb  = (uint32_t)(ks * 32 + lhi16);
            const uint32_t bkb2 = (uint32_t)(ks * 32) + bkb;

            uint32_t ah[4][4], al[4][4], bh[2][4], bl[2][4];
#pragma unroll
            for (int mi = 0; mi < 4; mi++) {
                uint32_t ra = (uint32_t)(mi * 16 + lr15) * RSB + akb;
                LDSM4(ah[mi][0], ah[mi][1], ah[mi][2], ah[mi][3], aHb + ra);
                if (NPROD == 3)
                    LDSM4(al[mi][0], al[mi][1], al[mi][2], al[mi][3], aLb + ra);
            }
#pragma unroll
            for (int pi = 0; pi < 2; pi++) {
                uint32_t rb = (uint32_t)(pi * 16 + bnsub + l7) * RSB + bkb2;
                LDSM4(bh[pi][0], bh[pi][1], bh[pi][2], bh[pi][3], bHb + rb);
                if (NPROD == 3)
                    LDSM4(bl[pi][0], bl[pi][1], bl[pi][2], bl[pi][3], bLb + rb);
            }
            // hh group first: fill the tensor queue
#pragma unroll
            for (int mi = 0; mi < 4; mi++)
#pragma unroll
                for (int ni = 0; ni < 4; ni++) {
                    const int pi = ni >> 1, j = (ni & 1) * 2;
                    float* a4 = acc[mi][ni];
                    MMA16816(a4[0], a4[1], a4[2], a4[3],
                             ah[mi][0], ah[mi][1], ah[mi][2], ah[mi][3],
                             bh[pi][j], bh[pi][j + 1]);
                }
            // issue next-stage loads under the tensor shadow
            if (ks == 0 && c + 1 < NC) load_stage(c + 1);
            if (NPROD == 3) {
#pragma unroll
                for (int mi = 0; mi < 4; mi++)
#pragma unroll
                    for (int ni = 0; ni < 4; ni++) {
                        const int pi = ni >> 1, j = (ni & 1) * 2;
                        float* a4 = acc[mi][ni];
                        MMA16816(a4[0], a4[1], a4[2], a4[3],
                                 ah[mi][0], ah[mi][1], ah[mi][2], ah[mi][3],
                                 bl[pi][j], bl[pi][j + 1]);
                    }
#pragma unroll
                for (int mi = 0; mi < 4; mi++)
#pragma unroll
                    for (int ni = 0; ni < 4; ni++) {
                        const int pi = ni >> 1, j = (ni & 1) * 2;
                        float* a4 = acc[mi][ni];
                        MMA16816(a4[0], a4[1], a4[2], a4[3],
                                 al[mi][0], al[mi][1], al[mi][2], al[mi][3],
                                 bh[pi][j], bh[pi][j + 1]);
                    }
            }
        }
    }
}

__device__ __forceinline__ void store_split(
    float (&acc)[4][4][4], h16* __restrict__ oh, h16* __restrict__ ol,
    int m0, int n0, int ldc)
{
    const int lane = threadIdx.x & 31;
    const int wm = (threadIdx.x >> 5) >> 2, wn = (threadIdx.x >> 5) & 3;
    const int gr = lane >> 2, gc = (lane & 3) << 1;
#pragma unroll
    for (int mi = 0; mi < 4; mi++) {
#pragma unroll
        for (int ni = 0; ni < 4; ni++) {
            const int rr = m0 + wm * 64 + mi * 16 + gr;
            const int cc = n0 + wn * 32 + ni * 8 + gc;
            float v0 = acc[mi][ni][0], v1 = acc[mi][ni][1];
            float v2 = acc[mi][ni][2], v3 = acc[mi][ni][3];
            h16 h0 = __float2half_rn(v0), h1 = __float2half_rn(v1);
            h16 h2 = __float2half_rn(v2), h3 = __float2half_rn(v3);
            __half2 hi01 = __halves2half2(h0, h1);
            __half2 hi23 = __halves2half2(h2, h3);
            __half2 lo01 = __halves2half2(__float2half_rn(v0 - __half2float(h0)),
                                          __float2half_rn(v1 - __half2float(h1)));
            __half2 lo23 = __halves2half2(__float2half_rn(v2 - __half2float(h2)),
                                          __float2half_rn(v3 - __half2float(h3)));
            *(__half2*)&oh[(size_t)rr * ldc + cc]       = hi01;
            *(__half2*)&ol[(size_t)rr * ldc + cc]       = lo01;
            *(__half2*)&oh[(size_t)(rr + 8) * ldc + cc] = hi23;
            *(__half2*)&ol[(size_t)(rr + 8) * ldc + cc] = lo23;
        }
    }
}

// ---------------- mega kernel: M | V | T | scores | PV(+softmax) -------------
__global__ __launch_bounds__(256, 2)
void mm_mega(float* __restrict__ out)
{
    extern __shared__ char smem[];
    const uint32_t sbase = smem_u32(smem);
    const uint32_t tiles = (sbase + 127u) & ~127u;
    const uint32_t rel = tiles - sbase;
    const int tid = threadIdx.x;
    const int bid = blockIdx.x;
    const int lane = tid & 31;
    const int wid = tid >> 5;
    const int wm = wid >> 2, wn = wid & 3;
    const int gr = lane >> 2, gc = (lane & 3) << 1;

    if (bid < 64) {                       // ---- M = Wk · Wq^T ----
        const int m0 = (bid >> 3) * 128, n0 = (bid & 7) * 128;
        float acc[4][4][4];
        gemm_core<3>(tiles,
                     g_Wkh + (size_t)m0 * D_DIM, g_Wkl + (size_t)m0 * D_DIM,
                     g_Wqh + (size_t)n0 * D_DIM, g_Wql + (size_t)n0 * D_DIM,
                     D_DIM, D_DIM / 32, acc);
        store_split(acc, g_Mth, g_Mtl, m0, n0, E_DIM);
        __threadfence(); __syncthreads();
        if (tid == 0) atomicAdd(&g_mdone, 1);
        return;
    }
    if (bid < 320) {                      // ---- V^T projection ----
        const int u = bid - 64;
        const int m0 = (u >> 5) * 128;    // d
        const int n0 = (u & 31) * 128;    // s
        float acc[4][4][4];
        gemm_core<1>(tiles,
                     g_Wvth + (size_t)m0 * E_DIM, nullptr,
                     g_xh + (size_t)n0 * E_DIM, nullptr,
                     E_DIM, E_DIM / 32, acc);
#pragma unroll
        for (int mi = 0; mi < 4; mi++)
#pragma unroll
            for (int ni = 0; ni < 4; ni++) {
                const int rr = m0 + wm * 64 + mi * 16 + gr;
                const int cc = n0 + wn * 32 + ni * 8 + gc;
                __half2 a = __halves2half2(__float2half_rn(acc[mi][ni][0]),
                                           __float2half_rn(acc[mi][ni][1]));
                __half2 b = __halves2half2(__float2half_rn(acc[mi][ni][2]),
                                           __float2half_rn(acc[mi][ni][3]));
                *(__half2*)&g_Vth[(size_t)rr * S_LEN + cc]       = a;
                *(__half2*)&g_Vth[(size_t)(rr + 8) * S_LEN + cc] = b;
            }
        __threadfence(); __syncthreads();
        if (tid == 0) atomicAdd(&g_vdone[u >> 5], 1);
        return;
    }
    if (bid < 576) {                      // ---- T = x · M (desc s) ----
        const int u = bid - 320;
        const int s = 31 - (u >> 3), b = u & 7;
        const int m0 = s * 128, n0 = b * 128;
        if (tid == 0) spin_ge(&g_mdone, 64);
        __syncthreads();
        float acc[4][4][4];
        gemm_core<3>(tiles,
                     g_xh + (size_t)m0 * E_DIM, g_xl + (size_t)m0 * E_DIM,
                     g_Mth + (size_t)n0 * E_DIM, g_Mtl + (size_t)n0 * E_DIM,
                     E_DIM, E_DIM / 32, acc);
        store_split(acc, g_Th, g_Tl, m0, n0, E_DIM);
        __threadfence(); __syncthreads();
        if (tid == 0) atomicAdd(&g_tdone[s], 1);
        return;
    }
    if (bid < 1104) {                     // ---- scores (desc br) ----
        const int u = bid - 576;
        int t = 527 - u;
        int br = (int)((sqrtf(8.0f * (float)t + 1.0f) - 1.0f) * 0.5f);
        while ((br + 1) * (br + 2) / 2 <= t) br++;
        while (br * (br + 1) / 2 > t) br--;
        const int bc = t - br * (br + 1) / 2;
        const int m0 = br * 128, n0 = bc * 128;

        if (tid == 0) spin_ge(&g_tdone[br], 8);
        __syncthreads();

        float acc[4][4][4];
        gemm_core<3>(tiles,
                     g_Th + (size_t)m0 * E_DIM, g_Tl + (size_t)m0 * E_DIM,
                     g_xh + (size_t)n0 * E_DIM, g_xl + (size_t)n0 * E_DIM,
                     E_DIM, E_DIM / 32, acc);

        const bool diag = (bc == br);
        const float scale = 1.0f / 32.0f;
#pragma unroll
        for (int mi = 0; mi < 4; mi++) {
            const int r0 = m0 + wm * 64 + mi * 16 + gr;
            const int r1 = r0 + 8;
            float mx0 = -3.4e38f, mx1 = -3.4e38f;
#pragma unroll
            for (int ni = 0; ni < 4; ni++) {
                const int cc = n0 + wn * 32 + ni * 8 + gc;
                float v0 = acc[mi][ni][0] * scale;
                float v1 = acc[mi][ni][1] * scale;
                float v2 = acc[mi][ni][2] * scale;
                float v3 = acc[mi][ni][3] * scale;
                *(float2*)&g_Pf[(size_t)r0 * S_LEN + cc] = make_float2(v0, v1);
                *(float2*)&g_Pf[(size_t)r1 * S_LEN + cc] = make_float2(v2, v3);
                if (!diag || cc     <= r0) mx0 = fmaxf(mx0, v0);
                if (!diag || cc + 1 <= r0) mx0 = fmaxf(mx0, v1);
                if (!diag || cc     <= r1) mx1 = fmaxf(mx1, v2);
                if (!diag || cc + 1 <= r1) mx1 = fmaxf(mx1, v3);
            }
            mx0 = fmaxf(mx0, __shfl_xor_sync(0xffffffffu, mx0, 1));
            mx0 = fmaxf(mx0, __shfl_xor_sync(0xffffffffu, mx0, 2));
            mx1 = fmaxf(mx1, __shfl_xor_sync(0xffffffffu, mx1, 1));
            mx1 = fmaxf(mx1, __shfl_xor_sync(0xffffffffu, mx1, 2));
            if ((lane & 3) == 0) {
                atomicMax(&g_rowmax[r0], encf(mx0));
                atomicMax(&g_rowmax[r1], encf(mx1));
            }
        }
        __threadfence(); __syncthreads();
        if (tid == 0) atomicAdd(&g_sdone[br], 1);
        return;
    }

    // ---- PV with fused softmax (desc br) ----
    {
        const int u = bid - 1104;
        const int br = 31 - (u >> 3), bc = u & 7;
        const int m0 = br * 128, n0 = bc * 128;
        const int NC = (br + 1) * 4;

        if (tid == 0) { spin_ge(&g_sdone[br], br + 1); spin_ge(&g_vdone[bc], 32); }
        __syncthreads();

        const int prow = tid >> 1, ph = tid & 1;
        const int grow = m0 + prow;
        const float mrow = decf(g_rowmax[grow]);
        float rs = 0.0f;

        float acc[4][4][4];
#pragma unroll
        for (int i = 0; i < 4; i++)
#pragma unroll
            for (int j = 0; j < 4; j++)
#pragma unroll
                for (int k = 0; k < 4; k++) acc[i][j][k] = 0.0f;

        // stage: A(fp16 P) 10240 | B(Vt) 10240 | STG(fp32 Pf) 18432 = 38912
        auto load_pv = [&](int c) {
            const uint32_t st = tiles + (uint32_t)(c & 1) * 38912u;
            const int k0 = c * 32;
#pragma unroll
            for (int j4 = 0; j4 < 4; j4++) {
                int j = tid + j4 * 256;
                int r = j >> 3, ck = j & 7;
                const void* g = g_Pf + (size_t)(m0 + r) * S_LEN + k0 + ck * 4;
                CP_ASYNC16(st + 20480u + (uint32_t)(r * 144 + ck * 16), g);
            }
#pragma unroll
            for (int j2 = 0; j2 < 2; j2++) {
                int j = tid + j2 * 256;
                int r = j >> 2, ck = j & 3;
                const void* g = g_Vth + (size_t)(n0 + r) * S_LEN + k0 + ck * 8;
                CP_ASYNC16(st + 10240u + (uint32_t)(r * RSB + ck * 16), g);
            }
            CP_COMMIT();
        };

        load_pv(0);

        const int lr15 = lane & 15;
        const int lhi16 = (lane >> 4) * 16;
        const int l7 = lane & 7;
        const int bmat = lane >> 3;
        const int bnsub = (bmat >> 1) * 8;
        const int bkb = (bmat & 1) * 16;

        for (int c = 0; c < NC; c++) {
            CP_WAIT(0);
            __syncthreads();
            // convert Pf chunk -> exp fp16 into A tile; accumulate rowsum
            {
                const uint32_t srel = rel + (uint32_t)(c & 1) * 38912u;
                const float* sp = (const float*)(smem + srel + 20480u
                                                 + prow * 144 + ph * 64);
                float4 f0 = ((const float4*)sp)[0];
                float4 f1 = ((const float4*)sp)[1];
                float4 f2 = ((const float4*)sp)[2];
                float4 f3 = ((const float4*)sp)[3];
                float v[16] = {f0.x, f0.y, f0.z, f0.w, f1.x, f1.y, f1.z, f1.w,
                               f2.x, f2.y, f2.z, f2.w, f3.x, f3.y, f3.z, f3.w};
                const int kg = c * 32 + ph * 16;
                uint32_t w[8];
#pragma unroll
                for (int e = 0; e < 8; e++) {
                    float a = (kg + 2 * e     <= grow) ? __expf(v[2 * e]     - mrow) : 0.0f;
                    float b = (kg + 2 * e + 1 <= grow) ? __expf(v[2 * e + 1] - mrow) : 0.0f;
                    __half2 hh = __floats2half2_rn(a, b);
                    float2 fb = __half22float2(hh);
                    rs += fb.x + fb.y;
                    w[e] = *(uint32_t*)&hh;
                }
                uint4 q0 = make_uint4(w[0], w[1], w[2], w[3]);
                uint4 q1 = make_uint4(w[4], w[5], w[6], w[7]);
                *(uint4*)(smem + srel + prow * RSB + ph * 32)      = q0;
                *(uint4*)(smem + srel + prow * RSB + ph * 32 + 16) = q1;
            }
            __syncthreads();

            const uint32_t st = tiles + (uint32_t)(c & 1) * 38912u;
            const uint32_t aB = st + (uint32_t)(wm * 64) * RSB;
            const uint32_t bB = st + 10240u + (uint32_t)(wn * 32) * RSB;
#pragma unroll
            for (int ks = 0; ks < 2; ks++) {
                const uint32_t akb  = (uint32_t)(ks * 32 + lhi16);
                const uint32_t bkb2 = (uint32_t)(ks * 32) + bkb;
                uint32_t ah[4][4], bh[2][4];
#pragma unroll
                for (int mi = 0; mi < 4; mi++) {
                    uint32_t ra = aB + (uint32_t)(mi * 16 + lr15) * RSB + akb;
                    LDSM4(ah[mi][0], ah[mi][1], ah[mi][2], ah[mi][3], ra);
                }
#pragma unroll
                for (int pi = 0; pi < 2; pi++) {
                    uint32_t rb = bB + (uint32_t)(pi * 16 + bnsub + l7) * RSB + bkb2;
                    LDSM4(bh[pi][0], bh[pi][1], bh[pi][2], bh[pi][3], rb);
                }
#pragma unroll
                for (int mi = 0; mi < 4; mi++)
#pragma unroll
                    for (int ni = 0; ni < 4; ni++) {
                        const int pi = ni >> 1, j = (ni & 1) * 2;
                        float* a4 = acc[mi][ni];
                        MMA16816(a4[0], a4[1], a4[2], a4[3],
                                 ah[mi][0], ah[mi][1], ah[mi][2], ah[mi][3],
                                 bh[pi][j], bh[pi][j + 1]);
                    }
                if (ks == 0 && c + 1 < NC) load_pv(c + 1);
            }
        }

        float rtot = rs + __shfl_xor_sync(0xffffffffu, rs, 1);
        if ((tid & 1) == 0)
            *(float*)(smem + rel + 77824u + prow * 4) = rtot;
        __syncthreads();
        const float* rsum = (const float*)(smem + rel + 77824u);
#pragma unroll
        for (int mi = 0; mi < 4; mi++) {
            const int r0 = m0 + wm * 64 + mi * 16 + gr;
            const float inv0 = 1.0f / rsum[r0 - m0];
            const float inv1 = 1.0f / rsum[r0 - m0 + 8];
#pragma unroll
            for (int ni = 0; ni < 4; ni++) {
                const int cc = n0 + wn * 32 + ni * 8 + gc;
                *(float2*)&out[(size_t)r0 * D_DIM + cc] =
                    make_float2(acc[mi][ni][0] * inv0, acc[mi][ni][1] * inv0);
                *(float2*)&out[(size_t)(r0 + 8) * D_DIM + cc] =
                    make_float2(acc[mi][ni][2] * inv1, acc[mi][ni][3] * inv1);
            }
        }
    }
}

// ---------------- host launcher ---------------------------------------------
extern "C" void kernel_launch(void* const* d_in, const int* in_sizes, int n_in,
                              void* d_out, int out_size)
{
    const float* x  = (const float*)d_in[0];
    const float* Wq = (const float*)d_in[1];
    const float* Wk = (const float*)d_in[2];
    const float* Wv = (const float*)d_in[3];
    float* out = (float*)d_out;

    cudaFuncSetAttribute(mm_mega, cudaFuncAttributeMaxDynamicSharedMemorySize,
                         SMEM_MEGA);

    // 1) prep: Wv^T tiles, vectorized splits of x/Wq/Wk, rowmax + flag resets
    prep<<<3072, 256>>>(x, Wq, Wk, Wv);
    // 2) everything else: one dataflow launch with tile-dependency flags
    mm_mega<<<1360, 256, SMEM_MEGA>>>(out);
}

// round 17
// speedup vs baseline: 1.5583x; 1.0057x over previous
#include <cuda_runtime.h>
#include <cuda_fp16.h>
#include <cstdint>
#include <math.h>

#define S_LEN 4096
#define E_DIM 1024
#define D_DIM 1024

typedef __half h16;

// ---------------- scratch (device globals; no allocation allowed) ----------
__device__ h16   g_xh[(size_t)S_LEN * E_DIM];
__device__ h16   g_xl[(size_t)S_LEN * E_DIM];
__device__ h16   g_Wqh[(size_t)E_DIM * D_DIM];
__device__ h16   g_Wql[(size_t)E_DIM * D_DIM];
__device__ h16   g_Wkh[(size_t)E_DIM * D_DIM];
__device__ h16   g_Wkl[(size_t)E_DIM * D_DIM];
__device__ h16   g_Wvth[(size_t)D_DIM * E_DIM];     // Wv^T hi only
__device__ h16   g_Mth[(size_t)E_DIM * E_DIM];      // (Wq Wk^T)^T split
__device__ h16   g_Mtl[(size_t)E_DIM * E_DIM];
__device__ h16   g_Th[(size_t)S_LEN * E_DIM];       // T = x M, split
__device__ h16   g_Tl[(size_t)S_LEN * E_DIM];
__device__ h16   g_Vth[(size_t)D_DIM * S_LEN];      // V^T fp16
__device__ float g_Pf[(size_t)S_LEN * S_LEN];       // raw scores (lower tri)
__device__ int   g_rowmax[S_LEN];
// dependency flags
__device__ int   g_mdone[8];               // per Mt-rowblock (8 tiles each)
__device__ int   g_vdone[8];
__device__ int   g_tdone[32];
__device__ int   g_sdone[32];

// ---------------- PTX helpers (sm_80-compatible only) -----------------------
__device__ __forceinline__ uint32_t smem_u32(const void* p) {
    uint32_t a;
    asm("{ .reg .u64 t; cvta.to.shared.u64 t, %1; cvt.u32.u64 %0, t; }" : "=r"(a) : "l"(p));
    return a;
}

#define CP_ASYNC16(saddr, gaddr) \
    asm volatile("cp.async.cg.shared.global [%0], [%1], 16;" \
                 :: "r"(saddr), "l"(gaddr) : "memory")
#define CP_COMMIT() asm volatile("cp.async.commit_group;" ::: "memory")
#define CP_WAIT(N)  asm volatile("cp.async.wait_group %0;" :: "n"(N) : "memory")

#define LDSM4(r0, r1, r2, r3, addr) \
    asm volatile("ldmatrix.sync.aligned.m8n8.x4.shared.b16 {%0,%1,%2,%3}, [%4];" \
                 : "=r"(r0), "=r"(r1), "=r"(r2), "=r"(r3) : "r"(addr))

#define MMA16816(c0, c1, c2, c3, a0, a1, a2, a3, b0, b1) \
    asm volatile("mma.sync.aligned.m16n8k16.row.col.f32.f16.f16.f32 " \
                 "{%0,%1,%2,%3}, {%4,%5,%6,%7}, {%8,%9}, {%0,%1,%2,%3};" \
                 : "+f"(c0), "+f"(c1), "+f"(c2), "+f"(c3) \
                 : "r"(a0), "r"(a1), "r"(a2), "r"(a3), "r"(b0), "r"(b1))

__device__ __forceinline__ int encf(float x) {
    int i = __float_as_int(x);
    return (i >= 0) ? i : (i ^ 0x7FFFFFFF);
}
__device__ __forceinline__ float decf(int i) {
    return __int_as_float((i >= 0) ? i : (i ^ 0x7FFFFFFF));
}

__device__ __forceinline__ void spin_ge(int* f, int tgt) {
    while (atomicAdd(f, 0) < tgt) __nanosleep(128);
}

// split a float4 into two half2 (hi) + two half2 (lo)
__device__ __forceinline__ void split4(float4 v, uint32_t& h01, uint32_t& h23,
                                       uint32_t& l01, uint32_t& l23)
{
    __half2 a = __floats2half2_rn(v.x, v.y);
    __half2 b = __floats2half2_rn(v.z, v.w);
    float2 fa = __half22float2(a), fb = __half22float2(b);
    __half2 la = __floats2half2_rn(v.x - fa.x, v.y - fa.y);
    __half2 lb = __floats2half2_rn(v.z - fb.x, v.w - fb.y);
    h01 = *(uint32_t*)&a; h23 = *(uint32_t*)&b;
    l01 = *(uint32_t*)&la; l23 = *(uint32_t*)&lb;
}

// ---------------- prep: Wv^T tiles + vectorized splits + flag resets ---------
__global__ __launch_bounds__(256)
void prep(const float* __restrict__ x, const float* __restrict__ Wq,
          const float* __restrict__ Wk, const float* __restrict__ Wv)
{
    __shared__ float t[32][33];
    if (blockIdx.x < 1024) {
        const int u = blockIdx.x;
        const int bx = (u & 31) * 32;   // d
        const int by = (u >> 5) * 32;   // e
        const int tx = threadIdx.x & 31, ty = threadIdx.x >> 5;
#pragma unroll
        for (int j = ty; j < 32; j += 8)
            t[j][tx] = Wv[(size_t)(by + j) * D_DIM + bx + tx];
        __syncthreads();
#pragma unroll
        for (int j = ty; j < 32; j += 8)
            g_Wvth[(size_t)(bx + j) * E_DIM + by + tx] = __float2half_rn(t[tx][j]);
        return;
    }
    if (blockIdx.x == 1024) {
        if (threadIdx.x < 32) { g_tdone[threadIdx.x] = 0; g_sdone[threadIdx.x] = 0; }
        if (threadIdx.x < 8)  { g_vdone[threadIdx.x] = 0; g_mdone[threadIdx.x] = 0; }
    }
    const int g = (blockIdx.x - 1024) * 256 + threadIdx.x;
    const int stride = 2048 * 256;
    if (g < S_LEN) g_rowmax[g] = 0x80000000;

    const int NX4 = (S_LEN * E_DIM) / 4;
    const int NW4 = (E_DIM * D_DIM) / 4;
    const float4* x4 = (const float4*)x;
    const float4* q4 = (const float4*)Wq;
    const float4* k4 = (const float4*)Wk;
    uint32_t h01, h23, l01, l23;
    for (int i = g; i < NX4; i += stride) {
        split4(x4[i], h01, h23, l01, l23);
        ((uint2*)g_xh)[i] = make_uint2(h01, h23);
        ((uint2*)g_xl)[i] = make_uint2(l01, l23);
    }
    for (int i = g; i < NW4; i += stride) {
        split4(q4[i], h01, h23, l01, l23);
        ((uint2*)g_Wqh)[i] = make_uint2(h01, h23);
        ((uint2*)g_Wql)[i] = make_uint2(l01, l23);
    }
    for (int i = g; i < NW4; i += stride) {
        split4(k4[i], h01, h23, l01, l23);
        ((uint2*)g_Wkh)[i] = make_uint2(h01, h23);
        ((uint2*)g_Wkl)[i] = make_uint2(l01, l23);
    }
}

// ---------------- GEMM core (round-12 exact) ----------------------------------
#define RSB     80
#define TILE_B  (128 * RSB)              // 10240
#define SMEM_MEGA (2 * 4 * TILE_B + 1024)   // 82944

template <int NPROD>
__device__ __forceinline__ void gemm_core(
    uint32_t tiles, const h16* __restrict__ A0, const h16* __restrict__ A1,
    const h16* __restrict__ B0, const h16* __restrict__ B1,
    int Ktot, int NC, float (&acc)[4][4][4])
{
    constexpr int NTILES = (NPROD == 3) ? 4 : 2;
    constexpr uint32_t STAGE_B = NTILES * TILE_B;

    const int tid = threadIdx.x;
    const int wid = tid >> 5;
    const int lane = tid & 31;
    const int wm = wid >> 2;
    const int wn = wid & 3;

#pragma unroll
    for (int i = 0; i < 4; i++)
#pragma unroll
        for (int j = 0; j < 4; j++)
#pragma unroll
            for (int k = 0; k < 4; k++) acc[i][j][k] = 0.0f;

    auto load_stage = [&](int c) {
        const uint32_t st = tiles + (uint32_t)(c & 1) * STAGE_B;
        const int k0 = c * 32;
        const h16* srcs[NTILES];
        if (NPROD == 3) {
            srcs[0] = A0 + k0; srcs[1] = A1 + k0;
            srcs[2] = B0 + k0; srcs[3] = B1 + k0;
        } else {
            srcs[0] = A0 + k0; srcs[1] = B0 + k0;
        }
#pragma unroll
        for (int t = 0; t < NTILES; t++) {
#pragma unroll
            for (int j2 = 0; j2 < 2; j2++) {
                int j = tid + j2 * 256;
                int row = j >> 2, ck = j & 3;
                const void* g = srcs[t] + (size_t)row * Ktot + ck * 8;
                uint32_t s = st + (uint32_t)t * TILE_B + row * RSB + ck * 16;
                CP_ASYNC16(s, g);
            }
        }
        CP_COMMIT();
    };

    load_stage(0);

    const int lr15 = lane & 15;
    const int lhi16 = (lane >> 4) * 16;
    const int l7 = lane & 7;
    const int bmat = lane >> 3;
    const int bnsub = (bmat >> 1) * 8;
    const int bkb = (bmat & 1) * 16;

    for (int c = 0; c < NC; c++) {
        CP_WAIT(0);
        __syncthreads();

        const uint32_t st = tiles + (uint32_t)(c & 1) * STAGE_B;
        const uint32_t aHb = st + (uint32_t)(wm * 64) * RSB;
        const uint32_t aLb = aHb + TILE_B;
        const uint32_t bHb = st + (uint32_t)(NTILES / 2) * TILE_B
                                + (uint32_t)(wn * 32) * RSB;
        const uint32_t bLb = bHb + TILE_B;

#pragma unroll
        for (int ks = 0; ks < 2; ks++) {
            const uint32_t akb  = (uint32_t)(ks * 32 + lhi16);
            const uint32_t bkb2 = (uint32_t)(ks * 32) + bkb;

            uint32_t ah[4][4], al[4][4], bh[2][4], bl[2][4];
#pragma unroll
            for (int mi = 0; mi < 4; mi++) {
                uint32_t ra = (uint32_t)(mi * 16 + lr15) * RSB + akb;
                LDSM4(ah[mi][0], ah[mi][1], ah[mi][2], ah[mi][3], aHb + ra);
                if (NPROD == 3)
                    LDSM4(al[mi][0], al[mi][1], al[mi][2], al[mi][3], aLb + ra);
            }
#pragma unroll
            for (int pi = 0; pi < 2; pi++) {
                uint32_t rb = (uint32_t)(pi * 16 + bnsub + l7) * RSB + bkb2;
                LDSM4(bh[pi][0], bh[pi][1], bh[pi][2], bh[pi][3], bHb + rb);
                if (NPROD == 3)
                    LDSM4(bl[pi][0], bl[pi][1], bl[pi][2], bl[pi][3], bLb + rb);
            }
            // hh group first: fill the tensor queue
#pragma unroll
            for (int mi = 0; mi < 4; mi++)
#pragma unroll
                for (int ni = 0; ni < 4; ni++) {
                    const int pi = ni >> 1, j = (ni & 1) * 2;
                    float* a4 = acc[mi][ni];
                    MMA16816(a4[0], a4[1], a4[2], a4[3],
                             ah[mi][0], ah[mi][1], ah[mi][2], ah[mi][3],
                             bh[pi][j], bh[pi][j + 1]);
                }
            // issue next-stage loads under the tensor shadow
            if (ks == 0 && c + 1 < NC) load_stage(c + 1);
            if (NPROD == 3) {
#pragma unroll
                for (int mi = 0; mi < 4; mi++)
#pragma unroll
                    for (int ni = 0; ni < 4; ni++) {
                        const int pi = ni >> 1, j = (ni & 1) * 2;
                        float* a4 = acc[mi][ni];
                        MMA16816(a4[0], a4[1], a4[2], a4[3],
                                 ah[mi][0], ah[mi][1], ah[mi][2], ah[mi][3],
                                 bl[pi][j], bl[pi][j + 1]);
                    }
#pragma unroll
                for (int mi = 0; mi < 4; mi++)
#pragma unroll
                    for (int ni = 0; ni < 4; ni++) {
                        const int pi = ni >> 1, j = (ni & 1) * 2;
                        float* a4 = acc[mi][ni];
                        MMA16816(a4[0], a4[1], a4[2], a4[3],
                                 al[mi][0], al[mi][1], al[mi][2], al[mi][3],
                                 bh[pi][j], bh[pi][j + 1]);
                    }
            }
        }
    }
}

__device__ __forceinline__ void store_split(
    float (&acc)[4][4][4], h16* __restrict__ oh, h16* __restrict__ ol,
    int m0, int n0, int ldc)
{
    const int lane = threadIdx.x & 31;
    const int wm = (threadIdx.x >> 5) >> 2, wn = (threadIdx.x >> 5) & 3;
    const int gr = lane >> 2, gc = (lane & 3) << 1;
#pragma unroll
    for (int mi = 0; mi < 4; mi++) {
#pragma unroll
        for (int ni = 0; ni < 4; ni++) {
            const int rr = m0 + wm * 64 + mi * 16 + gr;
            const int cc = n0 + wn * 32 + ni * 8 + gc;
            float v0 = acc[mi][ni][0], v1 = acc[mi][ni][1];
            float v2 = acc[mi][ni][2], v3 = acc[mi][ni][3];
            h16 h0 = __float2half_rn(v0), h1 = __float2half_rn(v1);
            h16 h2 = __float2half_rn(v2), h3 = __float2half_rn(v3);
            __half2 hi01 = __halves2half2(h0, h1);
            __half2 hi23 = __halves2half2(h2, h3);
            __half2 lo01 = __halves2half2(__float2half_rn(v0 - __half2float(h0)),
                                          __float2half_rn(v1 - __half2float(h1)));
            __half2 lo23 = __halves2half2(__float2half_rn(v2 - __half2float(h2)),
                                          __float2half_rn(v3 - __half2float(h3)));
            *(__half2*)&oh[(size_t)rr * ldc + cc]       = hi01;
            *(__half2*)&ol[(size_t)rr * ldc + cc]       = lo01;
            *(__half2*)&oh[(size_t)(rr + 8) * ldc + cc] = hi23;
            *(__half2*)&ol[(size_t)(rr + 8) * ldc + cc] = lo23;
        }
    }
}

// ---------------- mega kernel: M | V | T | scores | PV(+softmax) -------------
__global__ __launch_bounds__(256, 2)
void mm_mega(float* __restrict__ out)
{
    extern __shared__ char smem[];
    const uint32_t sbase = smem_u32(smem);
    const uint32_t tiles = (sbase + 127u) & ~127u;
    const uint32_t rel = tiles - sbase;
    const int tid = threadIdx.x;
    const int bid = blockIdx.x;
    const int lane = tid & 31;
    const int wid = tid >> 5;
    const int wm = wid >> 2, wn = wid & 3;
    const int gr = lane >> 2, gc = (lane & 3) << 1;

    if (bid < 64) {                       // ---- M = Wk · Wq^T ----
        const int m0 = (bid >> 3) * 128, n0 = (bid & 7) * 128;
        float acc[4][4][4];
        gemm_core<3>(tiles,
                     g_Wkh + (size_t)m0 * D_DIM, g_Wkl + (size_t)m0 * D_DIM,
                     g_Wqh + (size_t)n0 * D_DIM, g_Wql + (size_t)n0 * D_DIM,
                     D_DIM, D_DIM / 32, acc);
        store_split(acc, g_Mth, g_Mtl, m0, n0, E_DIM);
        __threadfence(); __syncthreads();
        if (tid == 0) atomicAdd(&g_mdone[bid >> 3], 1);
        return;
    }
    if (bid < 320) {                      // ---- V^T projection ----
        const int u = bid - 64;
        const int m0 = (u >> 5) * 128;    // d
        const int n0 = (u & 31) * 128;    // s
        float acc[4][4][4];
        gemm_core<1>(tiles,
                     g_Wvth + (size_t)m0 * E_DIM, nullptr,
                     g_xh + (size_t)n0 * E_DIM, nullptr,
                     E_DIM, E_DIM / 32, acc);
#pragma unroll
        for (int mi = 0; mi < 4; mi++)
#pragma unroll
            for (int ni = 0; ni < 4; ni++) {
                const int rr = m0 + wm * 64 + mi * 16 + gr;
                const int cc = n0 + wn * 32 + ni * 8 + gc;
                __half2 a = __halves2half2(__float2half_rn(acc[mi][ni][0]),
                                           __float2half_rn(acc[mi][ni][1]));
                __half2 b = __halves2half2(__float2half_rn(acc[mi][ni][2]),
                                           __float2half_rn(acc[mi][ni][3]));
                *(__half2*)&g_Vth[(size_t)rr * S_LEN + cc]       = a;
                *(__half2*)&g_Vth[(size_t)(rr + 8) * S_LEN + cc] = b;
            }
        __threadfence(); __syncthreads();
        if (tid == 0) atomicAdd(&g_vdone[u >> 5], 1);
        return;
    }
    if (bid < 576) {                      // ---- T = x · M (desc s) ----
        const int u = bid - 320;
        const int s = 31 - (u >> 3), b = u & 7;
        const int m0 = s * 128, n0 = b * 128;
        if (tid == 0) spin_ge(&g_mdone[b], 8);   // only the Mt rowblock we read
        __syncthreads();
        float acc[4][4][4];
        gemm_core<3>(tiles,
                     g_xh + (size_t)m0 * E_DIM, g_xl + (size_t)m0 * E_DIM,
                     g_Mth + (size_t)n0 * E_DIM, g_Mtl + (size_t)n0 * E_DIM,
                     E_DIM, E_DIM / 32, acc);
        store_split(acc, g_Th, g_Tl, m0, n0, E_DIM);
        __threadfence(); __syncthreads();
        if (tid == 0) atomicAdd(&g_tdone[s], 1);
        return;
    }
    if (bid < 1104) {                     // ---- scores (desc br) ----
        const int u = bid - 576;
        int t = 527 - u;
        int br = (int)((sqrtf(8.0f * (float)t + 1.0f) - 1.0f) * 0.5f);
        while ((br + 1) * (br + 2) / 2 <= t) br++;
        while (br * (br + 1) / 2 > t) br--;
        const int bc = t - br * (br + 1) / 2;
        const int m0 = br * 128, n0 = bc * 128;

        if (tid == 0) spin_ge(&g_tdone[br], 8);
        __syncthreads();

        float acc[4][4][4];
        gemm_core<3>(tiles,
                     g_Th + (size_t)m0 * E_DIM, g_Tl + (size_t)m0 * E_DIM,
                     g_xh + (size_t)n0 * E_DIM, g_xl + (size_t)n0 * E_DIM,
                     E_DIM, E_DIM / 32, acc);

        const bool diag = (bc == br);
        const float scale = 1.0f / 32.0f;
#pragma unroll
        for (int mi = 0; mi < 4; mi++) {
            const int r0 = m0 + wm * 64 + mi * 16 + gr;
            const int r1 = r0 + 8;
            float mx0 = -3.4e38f, mx1 = -3.4e38f;
#pragma unroll
            for (int ni = 0; ni < 4; ni++) {
                const int cc = n0 + wn * 32 + ni * 8 + gc;
                float v0 = acc[mi][ni][0] * scale;
                float v1 = acc[mi][ni][1] * scale;
                float v2 = acc[mi][ni][2] * scale;
                float v3 = acc[mi][ni][3] * scale;
                *(float2*)&g_Pf[(size_t)r0 * S_LEN + cc] = make_float2(v0, v1);
                *(float2*)&g_Pf[(size_t)r1 * S_LEN + cc] = make_float2(v2, v3);
                if (!diag || cc     <= r0) mx0 = fmaxf(mx0, v0);
                if (!diag || cc + 1 <= r0) mx0 = fmaxf(mx0, v1);
                if (!diag || cc     <= r1) mx1 = fmaxf(mx1, v2);
                if (!diag || cc + 1 <= r1) mx1 = fmaxf(mx1, v3);
            }
            mx0 = fmaxf(mx0, __shfl_xor_sync(0xffffffffu, mx0, 1));
            mx0 = fmaxf(mx0, __shfl_xor_sync(0xffffffffu, mx0, 2));
            mx1 = fmaxf(mx1, __shfl_xor_sync(0xffffffffu, mx1, 1));
            mx1 = fmaxf(mx1, __shfl_xor_sync(0xffffffffu, mx1, 2));
            if ((lane & 3) == 0) {
                atomicMax(&g_rowmax[r0], encf(mx0));
                atomicMax(&g_rowmax[r1], encf(mx1));
            }
        }
        __threadfence(); __syncthreads();
        if (tid == 0) atomicAdd(&g_sdone[br], 1);
        return;
    }

    // ---- PV with fused softmax (desc br) ----
    {
        const int u = bid - 1104;
        const int br = 31 - (u >> 3), bc = u & 7;
        const int m0 = br * 128, n0 = bc * 128;
        const int NC = (br + 1) * 4;

        if (tid == 0) { spin_ge(&g_sdone[br], br + 1); spin_ge(&g_vdone[bc], 32); }
        __syncthreads();

        const int prow = tid >> 1, ph = tid & 1;
        const int grow = m0 + prow;
        const float mrow = decf(g_rowmax[grow]);
        float rs = 0.0f;

        float acc[4][4][4];
#pragma unroll
        for (int i = 0; i < 4; i++)
#pragma unroll
            for (int j = 0; j < 4; j++)
#pragma unroll
                for (int k = 0; k < 4; k++) acc[i][j][k] = 0.0f;

        // stage: A(fp16 P) 10240 | B(Vt) 10240 | STG(fp32 Pf) 18432 = 38912
        auto load_pv = [&](int c) {
            const uint32_t st = tiles + (uint32_t)(c & 1) * 38912u;
            const int k0 = c * 32;
#pragma unroll
            for (int j4 = 0; j4 < 4; j4++) {
                int j = tid + j4 * 256;
                int r = j >> 3, ck = j & 7;
                const void* g = g_Pf + (size_t)(m0 + r) * S_LEN + k0 + ck * 4;
                CP_ASYNC16(st + 20480u + (uint32_t)(r * 144 + ck * 16), g);
            }
#pragma unroll
            for (int j2 = 0; j2 < 2; j2++) {
                int j = tid + j2 * 256;
                int r = j >> 2, ck = j & 3;
                const void* g = g_Vth + (size_t)(n0 + r) * S_LEN + k0 + ck * 8;
                CP_ASYNC16(st + 10240u + (uint32_t)(r * RSB + ck * 16), g);
            }
            CP_COMMIT();
        };

        load_pv(0);

        const int lr15 = lane & 15;
        const int lhi16 = (lane >> 4) * 16;
        const int l7 = lane & 7;
        const int bmat = lane >> 3;
        const int bnsub = (bmat >> 1) * 8;
        const int bkb = (bmat & 1) * 16;

        for (int c = 0; c < NC; c++) {
            CP_WAIT(0);
            __syncthreads();
            // convert Pf chunk -> exp fp16 into A tile; accumulate rowsum
            {
                const uint32_t srel = rel + (uint32_t)(c & 1) * 38912u;
                const float* sp = (const float*)(smem + srel + 20480u
                                                 + prow * 144 + ph * 64);
                float4 f0 = ((const float4*)sp)[0];
                float4 f1 = ((const float4*)sp)[1];
                float4 f2 = ((const float4*)sp)[2];
                float4 f3 = ((const float4*)sp)[3];
                float v[16] = {f0.x, f0.y, f0.z, f0.w, f1.x, f1.y, f1.z, f1.w,
                               f2.x, f2.y, f2.z, f2.w, f3.x, f3.y, f3.z, f3.w};
                const int kg = c * 32 + ph * 16;
                uint32_t w[8];
#pragma unroll
                for (int e = 0; e < 8; e++) {
                    float a = (kg + 2 * e     <= grow) ? __expf(v[2 * e]     - mrow) : 0.0f;
                    float b = (kg + 2 * e + 1 <= grow) ? __expf(v[2 * e + 1] - mrow) : 0.0f;
                    __half2 hh = __floats2half2_rn(a, b);
                    float2 fb = __half22float2(hh);
                    rs += fb.x + fb.y;
                    w[e] = *(uint32_t*)&hh;
                }
                uint4 q0 = make_uint4(w[0], w[1], w[2], w[3]);
                uint4 q1 = make_uint4(w[4], w[5], w[6], w[7]);
                *(uint4*)(smem + srel + prow * RSB + ph * 32)      = q0;
                *(uint4*)(smem + srel + prow * RSB + ph * 32 + 16) = q1;
            }
            __syncthreads();

            const uint32_t st = tiles + (uint32_t)(c & 1) * 38912u;
            const uint32_t aB = st + (uint32_t)(wm * 64) * RSB;
            const uint32_t bB = st + 10240u + (uint32_t)(wn * 32) * RSB;
#pragma unroll
            for (int ks = 0; ks < 2; ks++) {
                const uint32_t akb  = (uint32_t)(ks * 32 + lhi16);
                const uint32_t bkb2 = (uint32_t)(ks * 32) + bkb;
                uint32_t ah[4][4], bh[2][4];
#pragma unroll
                for (int mi = 0; mi < 4; mi++) {
                    uint32_t ra = aB + (uint32_t)(mi * 16 + lr15) * RSB + akb;
                    LDSM4(ah[mi][0], ah[mi][1], ah[mi][2], ah[mi][3], ra);
                }
#pragma unroll
                for (int pi = 0; pi < 2; pi++) {
                    uint32_t rb = bB + (uint32_t)(pi * 16 + bnsub + l7) * RSB + bkb2;
                    LDSM4(bh[pi][0], bh[pi][1], bh[pi][2], bh[pi][3], rb);
                }
#pragma unroll
                for (int mi = 0; mi < 4; mi++)
#pragma unroll
                    for (int ni = 0; ni < 4; ni++) {
                        const int pi = ni >> 1, j = (ni & 1) * 2;
                        float* a4 = acc[mi][ni];
                        MMA16816(a4[0], a4[1], a4[2], a4[3],
                                 ah[mi][0], ah[mi][1], ah[mi][2], ah[mi][3],
                                 bh[pi][j], bh[pi][j + 1]);
                    }
                if (ks == 0 && c + 1 < NC) load_pv(c + 1);
            }
        }

        float rtot = rs + __shfl_xor_sync(0xffffffffu, rs, 1);
        if ((tid & 1) == 0)
            *(float*)(smem + rel + 77824u + prow * 4) = rtot;
        __syncthreads();
        const float* rsum = (const float*)(smem + rel + 77824u);
#pragma unroll
        for (int mi = 0; mi < 4; mi++) {
            const int r0 = m0 + wm * 64 + mi * 16 + gr;
            const float inv0 = 1.0f / rsum[r0 - m0];
            const float inv1 = 1.0f / rsum[r0 - m0 + 8];
#pragma unroll
            for (int ni = 0; ni < 4; ni++) {
                const int cc = n0 + wn * 32 + ni * 8 + gc;
                *(float2*)&out[(size_t)r0 * D_DIM + cc] =
                    make_float2(acc[mi][ni][0] * inv0, acc[mi][ni][1] * inv0);
                *(float2*)&out[(size_t)(r0 + 8) * D_DIM + cc] =
                    make_float2(acc[mi][ni][2] * inv1, acc[mi][ni][3] * inv1);
            }
        }
    }
}

// ---------------- host launcher ---------------------------------------------
extern "C" void kernel_launch(void* const* d_in, const int* in_sizes, int n_in,
                              void* d_out, int out_size)
{
    const float* x  = (const float*)d_in[0];
    const float* Wq = (const float*)d_in[1];
    const float* Wk = (const float*)d_in[2];
    const float* Wv = (const float*)d_in[3];
    float* out = (float*)d_out;

    cudaFuncSetAttribute(mm_mega, cudaFuncAttributeMaxDynamicSharedMemorySize,
                         SMEM_MEGA);

    // 1) prep: Wv^T tiles, vectorized splits of x/Wq/Wk, rowmax + flag resets
    prep<<<3072, 256>>>(x, Wq, Wk, Wv);
    // 2) everything else: one dataflow launch with tile-dependency flags
    mm_mega<<<1360, 256, SMEM_MEGA>>>(out);
}